// round 16
// baseline (speedup 1.0000x reference)
#include <cuda_runtime.h>
#include <cstdint>
#include <cstddef>

// Problem constants
#define NB   8
#define CB   128
#define NC   1024          // NB*CB
#define HH   160
#define WW   160
#define NA   180
#define NR   180
#define AR   (NA*NR)       // 32400
#define PIX  (HH*WW)       // 25600
#define WR   16            // staged rho-window rows (16x8 tile span <= 15)
#define PH   3             // angles per staging phase
#define NPHASE (NA/PH)     // 60
#define TPB  512
#define BUFB (PH*WR*512)   // 24576 B per buffer

// Scratch in __device__ globals (no allocation allowed)
__device__ float         g_T[(size_t)AR * NC];       // transposed: T[a][r][nc]
__device__ unsigned char g_idx[(size_t)NA * PIX];    // r index table [a][y][x]
__device__ double        g_tab[2 * NA];              // cos/irho, sin/irho

// sorted walk orders (8 px of a 4x2 block, px = x + 4y), packed 3b per slot
__device__ const unsigned c_ord[8] = {
    0u|(4u<<3)|(1u<<6)|(5u<<9)|(2u<<12)|(6u<<15)|(3u<<18)|(7u<<21),  // [0,45)
    0u|(1u<<3)|(4u<<6)|(2u<<9)|(5u<<12)|(3u<<15)|(6u<<18)|(7u<<21),  // [45,63)
    0u|(1u<<3)|(2u<<6)|(4u<<9)|(3u<<12)|(5u<<15)|(6u<<18)|(7u<<21),  // [63,72)
    0u|(1u<<3)|(2u<<6)|(3u<<9)|(4u<<12)|(5u<<15)|(6u<<18)|(7u<<21),  // [72,90)
    3u|(2u<<3)|(1u<<6)|(0u<<9)|(7u<<12)|(6u<<15)|(5u<<18)|(4u<<21),  // [90,108)
    3u|(2u<<3)|(1u<<6)|(7u<<9)|(0u<<12)|(6u<<15)|(5u<<18)|(4u<<21),  // [108,117)
    3u|(2u<<3)|(7u<<6)|(1u<<9)|(6u<<12)|(0u<<15)|(5u<<18)|(4u<<21),  // [117,135)
    3u|(7u<<3)|(2u<<6)|(6u<<9)|(1u<<12)|(5u<<15)|(0u<<18)|(4u<<21)   // [135,180)
};

// ---------------------------------------------------------------------------
// Kernel 0: trig table (fp64, once)
// ---------------------------------------------------------------------------
__global__ void tab_kernel()
{
    int a = threadIdx.x;
    if (a < NA) {
        const double PI = 3.14159265358979323846;
        double th = (double)a * (PI / 180.0);
        double irho = 227.0 / 180.0;   // (int(sqrt(160^2+160^2))+1)/180
        g_tab[a]      = cos(th) / irho;
        g_tab[NA + a] = sin(th) / irho;
    }
}

// ---------------------------------------------------------------------------
// Kernel 1: rho-index table, vectorized 4 px/thread with u32 stores.
//   numpy-exact: each x-product is an independent RN dmul; the y-product is
//   identical across the 4 pixels (same elementwise op in numpy) -> hoisted.
// ---------------------------------------------------------------------------
__global__ void build_idx_kernel()
{
    const int a = blockIdx.y;
    double tc = g_tab[a], ts = g_tab[NA + a];
    int q = blockIdx.x * 256 + threadIdx.x;      // u32 index: 6400 per angle
    int p4 = q * 4;
    int y = p4 / WW, x = p4 - y * WW;            // x is a multiple of 4
    double yterm = __dmul_rn((double)(y - 80), ts);
    unsigned ob = 0;
    #pragma unroll
    for (int k = 0; k < 4; k++) {
        double v = __dadd_rn(__dmul_rn((double)(x + k - 80), tc), yterm);
        int r = (int)rint(v) + 90;
        r = min(NR - 1, max(0, r));
        ob |= ((unsigned)r) << (8 * k);
    }
    ((unsigned*)g_idx)[(size_t)a * (PIX / 4) + q] = ob;
}

// ---------------------------------------------------------------------------
// Kernel 2: vectorized transpose In[NC][AR] -> T[AR][NC].
//   Tile = 48 ar x 32 nc. Load: float4 along ar; store: float4 along nc,
//   128B-coalesced. Padded smem, conflict-free.
// ---------------------------------------------------------------------------
__global__ void __launch_bounds__(384) transpose_kernel(const float* __restrict__ in)
{
    __shared__ float tile[48][33];
    const int ar0 = blockIdx.x * 48;
    const int nc0 = blockIdx.y * 32;
    const int ty = threadIdx.x;          // 0..31 : nc within tile
    const int tx = threadIdx.y;          // 0..11 : group of 4 ar

    float4 v = *(const float4*)&in[(size_t)(nc0 + ty) * AR + ar0 + 4 * tx];
    tile[4 * tx + 0][ty] = v.x;
    tile[4 * tx + 1][ty] = v.y;
    tile[4 * tx + 2][ty] = v.z;
    tile[4 * tx + 3][ty] = v.w;
    __syncthreads();

    const int tid = ty + 32 * tx;        // 0..383
    const int i = tid >> 3;              // 0..47 : ar within tile
    const int j = tid & 7;               // 0..7  : group of 4 nc
    float4 o;
    o.x = tile[i][4 * j + 0];
    o.y = tile[i][4 * j + 1];
    o.z = tile[i][4 * j + 2];
    o.w = tile[i][4 * j + 3];
    *(float4*)&g_T[(size_t)(ar0 + i) * NC + nc0 + 4 * j] = o;
}

// ---------------------------------------------------------------------------
// Kernel 3: main inverse-Hough (R9 core; staging now span-predicated).
//   CTA = 16x8 pixel tile x 128 ch, 512 thr = 16 warps, 2 CTAs/SM.
//   Warp = one 4x2 pixel block; lane = 4 consecutive channels.
//   Sorted-by-rho walk per angle class => loads = range+1 (minimum).
//   Double-buffered cp.async staging; granules with row >= span[a] are
//   skipped (avg span ~12 of 16 -> -24% staging traffic). Base, records
//   and consume are byte-identical to the 457us R9 kernel.
// ---------------------------------------------------------------------------
__device__ __forceinline__ void cp16(unsigned smem_addr, const void* gptr)
{
    asm volatile("cp.async.cg.shared.global [%0], [%1], 16;\n"
                 :: "r"(smem_addr), "l"(gptr));
}

__global__ void __launch_bounds__(TPB, 2) iht_main_kernel(float* __restrict__ out)
{
    __shared__ __align__(16) char sbuf[2][BUFB];     // 49152 B
    __shared__ unsigned sw[16 * NA];                 // 11520 B
    __shared__ unsigned char sbase[192];
    __shared__ unsigned char sspan[192];

    const int tid = threadIdx.x;
    const int x0 = blockIdx.x * 16;
    const int y0 = blockIdx.y * 8;
    const int cz0 = blockIdx.z * 128;
    const int lane = tid & 31;
    const int w = tid >> 5;                          // warp = pixel block id

    // ---- per-angle window base + span (corners of the affine field) ----
    if (tid < NA) {
        const unsigned char* s = g_idx + (size_t)tid * PIX + y0 * WW + x0;
        int c0v = s[0], c1v = s[15], c2v = s[7 * WW], c3v = s[7 * WW + 15];
        int mn = min(min(c0v, c1v), min(c2v, c3v));
        int mx = max(max(c0v, c1v), max(c2v, c3v));
        int b = min(mn, NR - WR);
        sbase[tid] = (unsigned char)b;
        sspan[tid] = (unsigned char)(mx - b + 1);    // <= WR always
    }
    __syncthreads();

    // ---- staging (span-predicated granules) ----
    auto stage = [&](int f) {
        int a0 = f * PH;
        unsigned sd = (unsigned)__cvta_generic_to_shared(sbuf[f & 1]);
        #pragma unroll
        for (int it = 0; it < 3; it++) {
            int e = tid + it * TPB;                  // 1536 granules of 16B
            int s   = e >> 9;
            int rem = e & 511;
            int row = rem >> 5;
            int c   = rem & 31;
            int a = a0 + s;
            if (row < (int)sspan[a]) {
                int r = (int)sbase[a] + row;
                cp16(sd + (e << 4),
                     g_T + ((size_t)a * NR + r) * NC + cz0 + c * 4);
            }
        }
        asm volatile("cp.async.commit_group;\n" ::: "memory");
    };

    stage(0);

    // ---- build packed sorted-walk records: sw[blk*180 + a] ----
    // STRICT boundaries: must match the DOSEG consume ranges exactly
    for (int i = tid; i < 16 * NA; i += TPB) {
        int blk = i & 15, a = i >> 4;
        int cls = a < 45 ? 0 : a < 63 ? 1 : a < 72 ? 2 : a < 90 ? 3
                : a < 108 ? 4 : a < 117 ? 5 : a < 135 ? 6 : 7;
        unsigned ord = c_ord[cls];
        const unsigned char* s = g_idx + (size_t)a * PIX
                                 + (y0 + 2 * (blk >> 2)) * WW + x0 + 4 * (blk & 3);
        unsigned t0 = *(const unsigned*)s;           // y=0 row: px 0..3
        unsigned t1 = *(const unsigned*)(s + WW);    // y=1 row: px 4..7
        int p = ord & 7;
        int prev = (int)(((p < 4 ? t0 : t1) >> (8 * (p & 3))) & 255u);
        unsigned wv = (unsigned)(prev - (int)sbase[a]);
        #pragma unroll
        for (int k = 1; k < 8; k++) {
            p = (ord >> (3 * k)) & 7;
            int cur = (int)(((p < 4 ? t0 : t1) >> (8 * (p & 3))) & 255u);
            wv |= ((unsigned)((cur - prev) & 7)) << (5 + 3 * (k - 1));
            prev = cur;
        }
        sw[blk * NA + a] = wv;
    }
    __syncthreads();

    // ---- accumulators: 8 px x 4 ch = 16 u64 (px index = x + 4y) ----
    unsigned long long acc[16];
    #pragma unroll
    for (int i = 0; i < 16; i++) acc[i] = 0ull;

#define STEP0(PX)                                                             \
    asm volatile("{\n\t"                                                      \
        ".reg .u32 rr;\n\t"                                                   \
        "bfe.u32 rr, %5, 0, 5;\n\t"                                           \
        "mad.lo.u32 %4, rr, 512, %6;\n\t"                                     \
        "ld.shared.v2.u64 {%2, %3}, [%4];\n\t"                                \
        "add.rn.f32x2 %0, %0, %2;\n\t"                                        \
        "add.rn.f32x2 %1, %1, %3;\n\t"                                        \
        "}"                                                                   \
        : "+l"(acc[2*(PX)]), "+l"(acc[2*(PX)+1]),                             \
          "+l"(v0), "+l"(v1), "=r"(ad)                                        \
        : "r"(wv), "r"(sA))

#define STEPD(PX, K)                                                          \
    asm volatile("{\n\t"                                                      \
        ".reg .pred p;\n\t .reg .s32 d;\n\t"                                  \
        "bfe.s32 d, %5, %6, 3;\n\t"                                           \
        "setp.ne.s32 p, d, 0;\n\t"                                            \
        "mad.lo.s32 %4, d, 512, %4;\n\t"                                      \
        "@p ld.shared.v2.u64 {%2, %3}, [%4];\n\t"                             \
        "add.rn.f32x2 %0, %0, %2;\n\t"                                        \
        "add.rn.f32x2 %1, %1, %3;\n\t"                                        \
        "}"                                                                   \
        : "+l"(acc[2*(PX)]), "+l"(acc[2*(PX)+1]),                             \
          "+l"(v0), "+l"(v1), "+r"(ad)                                        \
        : "r"(wv), "n"(5 + 3*((K)-1)))

#define DOSEG(F0, F1, Q0,Q1,Q2,Q3,Q4,Q5,Q6,Q7)                                \
    for (int f = (F0); f < (F1); f++) {                                       \
        asm volatile("cp.async.wait_group 0;\n" ::: "memory");                \
        __syncthreads();                                                      \
        if (f + 1 < NPHASE) stage(f + 1);                                     \
        unsigned bufa = bufa0 + (unsigned)((f & 1) * BUFB);                   \
        _Pragma("unroll")                                                     \
        for (int s2 = 0; s2 < PH; s2++) {                                     \
            unsigned wv = sw[swb + f * PH + s2];                              \
            unsigned sA = bufa + (unsigned)(s2 * (WR * 512));                 \
            unsigned long long v0 = 0, v1 = 0;                                \
            unsigned ad;                                                      \
            STEP0(Q0);    STEPD(Q1,1); STEPD(Q2,2); STEPD(Q3,3);              \
            STEPD(Q4,4);  STEPD(Q5,5); STEPD(Q6,6); STEPD(Q7,7);              \
        }                                                                     \
    }

    const unsigned swb = w * NA;
    unsigned bufa0 = (unsigned)__cvta_generic_to_shared(sbuf[0]) + (lane << 4);

    DOSEG( 0, 15, 0,4,1,5,2,6,3,7);   // a 0-44
    DOSEG(15, 21, 0,1,4,2,5,3,6,7);   // a 45-62
    DOSEG(21, 24, 0,1,2,4,3,5,6,7);   // a 63-71
    DOSEG(24, 30, 0,1,2,3,4,5,6,7);   // a 72-89
    DOSEG(30, 36, 3,2,1,0,7,6,5,4);   // a 90-107
    DOSEG(36, 39, 3,2,1,7,0,6,5,4);   // a 108-116
    DOSEG(39, 45, 3,2,7,1,6,0,5,4);   // a 117-134
    DOSEG(45, 60, 3,7,2,6,1,5,0,4);   // a 135-179
#undef DOSEG
#undef STEPD
#undef STEP0

    // ---- epilogue: per ch, per row: float4 over the 4-wide block ----
    const int gx = x0 + 4 * (w & 3);
    const int gy = y0 + 2 * (w >> 2);
    const int c0 = cz0 + lane * 4;
    #pragma unroll
    for (int y = 0; y < 2; y++) {
        #pragma unroll
        for (int cc = 0; cc < 4; cc++) {
            int half = cc & 1, sel = cc >> 1;
            float4 o;
            unsigned long long s0 = acc[(0 + 4*y)*2 + sel];
            unsigned long long s1 = acc[(1 + 4*y)*2 + sel];
            unsigned long long s2 = acc[(2 + 4*y)*2 + sel];
            unsigned long long s3 = acc[(3 + 4*y)*2 + sel];
            o.x = __uint_as_float(half ? (unsigned)(s0 >> 32) : (unsigned)s0);
            o.y = __uint_as_float(half ? (unsigned)(s1 >> 32) : (unsigned)s1);
            o.z = __uint_as_float(half ? (unsigned)(s2 >> 32) : (unsigned)s2);
            o.w = __uint_as_float(half ? (unsigned)(s3 >> 32) : (unsigned)s3);
            *(float4*)(out + (size_t)(c0 + cc) * PIX + (gy + y) * WW + gx) = o;
        }
    }
}

// ---------------------------------------------------------------------------
extern "C" void kernel_launch(void* const* d_in, const int* in_sizes, int n_in,
                              void* d_out, int out_size)
{
    const float* hough = (const float*)d_in[0];
    float* out = (float*)d_out;

    tab_kernel<<<1, 256>>>();
    build_idx_kernel<<<dim3(PIX / 1024, NA), 256>>>();
    transpose_kernel<<<dim3(AR / 48, NC / 32), dim3(32, 12)>>>(hough);
    iht_main_kernel<<<dim3(10, 20, 8), TPB>>>(out);
}

// round 17
// speedup vs baseline: 1.0399x; 1.0399x over previous
#include <cuda_runtime.h>
#include <cstdint>
#include <cstddef>

// Problem constants
#define NB   8
#define CB   128
#define NC   1024          // NB*CB
#define HH   160
#define WW   160
#define NA   180
#define NR   180
#define AR   (NA*NR)       // 32400
#define PIX  (HH*WW)       // 25600
#define WR   16            // staged rho-window rows (16x8 tile span <= 15)
#define PH   3             // angles per staging phase
#define NPHASE (NA/PH)     // 60
#define TPB  512
#define BUFB (PH*WR*512)   // 24576 B per buffer

// Scratch in __device__ globals (no allocation allowed)
__device__ float         g_T[(size_t)AR * NC];       // transposed: T[a][r][nc]
__device__ unsigned char g_idx[(size_t)NA * PIX];    // r index table [a][y][x]
__device__ double        g_tab[2 * NA];              // cos/irho, sin/irho

// sorted walk orders (8 px of a 4x2 block, px = x + 4y), packed 3b per slot
__device__ const unsigned c_ord[8] = {
    0u|(4u<<3)|(1u<<6)|(5u<<9)|(2u<<12)|(6u<<15)|(3u<<18)|(7u<<21),  // [0,45)
    0u|(1u<<3)|(4u<<6)|(2u<<9)|(5u<<12)|(3u<<15)|(6u<<18)|(7u<<21),  // [45,63)
    0u|(1u<<3)|(2u<<6)|(4u<<9)|(3u<<12)|(5u<<15)|(6u<<18)|(7u<<21),  // [63,72)
    0u|(1u<<3)|(2u<<6)|(3u<<9)|(4u<<12)|(5u<<15)|(6u<<18)|(7u<<21),  // [72,90)
    3u|(2u<<3)|(1u<<6)|(0u<<9)|(7u<<12)|(6u<<15)|(5u<<18)|(4u<<21),  // [90,108)
    3u|(2u<<3)|(1u<<6)|(7u<<9)|(0u<<12)|(6u<<15)|(5u<<18)|(4u<<21),  // [108,117)
    3u|(2u<<3)|(7u<<6)|(1u<<9)|(6u<<12)|(0u<<15)|(5u<<18)|(4u<<21),  // [117,135)
    3u|(7u<<3)|(2u<<6)|(6u<<9)|(1u<<12)|(5u<<15)|(0u<<18)|(4u<<21)   // [135,180)
};

// ---------------------------------------------------------------------------
// Kernel 0: trig table (fp64, once)
// ---------------------------------------------------------------------------
__global__ void tab_kernel()
{
    int a = threadIdx.x;
    if (a < NA) {
        const double PI = 3.14159265358979323846;
        double th = (double)a * (PI / 180.0);
        double irho = 227.0 / 180.0;   // (int(sqrt(160^2+160^2))+1)/180
        g_tab[a]      = cos(th) / irho;
        g_tab[NA + a] = sin(th) / irho;
    }
}

// ---------------------------------------------------------------------------
// Kernel 1: rho-index table, vectorized 4 px/thread with u32 stores.
//   numpy-exact: each x-product is an independent RN dmul; the y-product is
//   identical across the 4 pixels (same elementwise op in numpy) -> hoisted.
// ---------------------------------------------------------------------------
__global__ void build_idx_kernel()
{
    const int a = blockIdx.y;
    double tc = g_tab[a], ts = g_tab[NA + a];
    int q = blockIdx.x * 256 + threadIdx.x;      // u32 index: 6400 per angle
    int p4 = q * 4;
    int y = p4 / WW, x = p4 - y * WW;            // x is a multiple of 4
    double yterm = __dmul_rn((double)(y - 80), ts);
    unsigned ob = 0;
    #pragma unroll
    for (int k = 0; k < 4; k++) {
        double v = __dadd_rn(__dmul_rn((double)(x + k - 80), tc), yterm);
        int r = (int)rint(v) + 90;
        r = min(NR - 1, max(0, r));
        ob |= ((unsigned)r) << (8 * k);
    }
    ((unsigned*)g_idx)[(size_t)a * (PIX / 4) + q] = ob;
}

// ---------------------------------------------------------------------------
// Kernel 2: vectorized transpose In[NC][AR] -> T[AR][NC].
//   Tile = 48 ar x 32 nc. Load: float4 along ar; store: float4 along nc,
//   128B-coalesced. Padded smem, conflict-free.
// ---------------------------------------------------------------------------
__global__ void __launch_bounds__(384) transpose_kernel(const float* __restrict__ in)
{
    __shared__ float tile[48][33];
    const int ar0 = blockIdx.x * 48;
    const int nc0 = blockIdx.y * 32;
    const int ty = threadIdx.x;          // 0..31 : nc within tile
    const int tx = threadIdx.y;          // 0..11 : group of 4 ar

    float4 v = *(const float4*)&in[(size_t)(nc0 + ty) * AR + ar0 + 4 * tx];
    tile[4 * tx + 0][ty] = v.x;
    tile[4 * tx + 1][ty] = v.y;
    tile[4 * tx + 2][ty] = v.z;
    tile[4 * tx + 3][ty] = v.w;
    __syncthreads();

    const int tid = ty + 32 * tx;        // 0..383
    const int i = tid >> 3;              // 0..47 : ar within tile
    const int j = tid & 7;               // 0..7  : group of 4 nc
    float4 o;
    o.x = tile[i][4 * j + 0];
    o.y = tile[i][4 * j + 1];
    o.z = tile[i][4 * j + 2];
    o.w = tile[i][4 * j + 3];
    *(float4*)&g_T[(size_t)(ar0 + i) * NC + nc0 + 4 * j] = o;
}

// ---------------------------------------------------------------------------
// Kernel 3: main inverse-Hough (R9/R15 core, byte-identical — 456.6 us).
//   CTA = 16x8 pixel tile x 128 ch, 512 thr = 16 warps, 2 CTAs/SM.
//   Warp = one 4x2 pixel block; lane = 4 consecutive channels.
//   Sorted-by-rho walk per angle class => loads = range+1 (minimum).
//   Double-buffered cp.async staging, FIXED span (uniform granule loop —
//   the span-predicated variant measured +23us; reverted).
// ---------------------------------------------------------------------------
__device__ __forceinline__ void cp16(unsigned smem_addr, const void* gptr)
{
    asm volatile("cp.async.cg.shared.global [%0], [%1], 16;\n"
                 :: "r"(smem_addr), "l"(gptr));
}

__global__ void __launch_bounds__(TPB, 2) iht_main_kernel(float* __restrict__ out)
{
    __shared__ __align__(16) char sbuf[2][BUFB];     // 49152 B
    __shared__ unsigned sw[16 * NA];                 // 11520 B
    __shared__ unsigned char sbase[192];

    const int tid = threadIdx.x;
    const int x0 = blockIdx.x * 16;
    const int y0 = blockIdx.y * 8;
    const int cz0 = blockIdx.z * 128;
    const int lane = tid & 31;
    const int w = tid >> 5;                          // warp = pixel block id

    // ---- per-angle window base (min over tile corners; affine => corners) ----
    if (tid < NA) {
        const unsigned char* s = g_idx + (size_t)tid * PIX + y0 * WW + x0;
        int m = min(min((int)s[0], (int)s[15]),
                    min((int)s[7 * WW], (int)s[7 * WW + 15]));
        sbase[tid] = (unsigned char)min(m, NR - WR);
    }
    __syncthreads();

    // ---- staging ----
    auto stage = [&](int f) {
        int a0 = f * PH;
        unsigned sd = (unsigned)__cvta_generic_to_shared(sbuf[f & 1]);
        #pragma unroll
        for (int it = 0; it < 3; it++) {
            int e = tid + it * TPB;                  // 1536 granules of 16B
            int s   = e >> 9;
            int rem = e & 511;
            int row = rem >> 5;
            int c   = rem & 31;
            int a = a0 + s;
            int r = (int)sbase[a] + row;
            cp16(sd + (e << 4),
                 g_T + ((size_t)a * NR + r) * NC + cz0 + c * 4);
        }
        asm volatile("cp.async.commit_group;\n" ::: "memory");
    };

    stage(0);

    // ---- build packed sorted-walk records: sw[blk*180 + a] ----
    // STRICT boundaries: must match the DOSEG consume ranges exactly
    for (int i = tid; i < 16 * NA; i += TPB) {
        int blk = i & 15, a = i >> 4;
        int cls = a < 45 ? 0 : a < 63 ? 1 : a < 72 ? 2 : a < 90 ? 3
                : a < 108 ? 4 : a < 117 ? 5 : a < 135 ? 6 : 7;
        unsigned ord = c_ord[cls];
        const unsigned char* s = g_idx + (size_t)a * PIX
                                 + (y0 + 2 * (blk >> 2)) * WW + x0 + 4 * (blk & 3);
        unsigned t0 = *(const unsigned*)s;           // y=0 row: px 0..3
        unsigned t1 = *(const unsigned*)(s + WW);    // y=1 row: px 4..7
        int p = ord & 7;
        int prev = (int)(((p < 4 ? t0 : t1) >> (8 * (p & 3))) & 255u);
        unsigned wv = (unsigned)(prev - (int)sbase[a]);
        #pragma unroll
        for (int k = 1; k < 8; k++) {
            p = (ord >> (3 * k)) & 7;
            int cur = (int)(((p < 4 ? t0 : t1) >> (8 * (p & 3))) & 255u);
            wv |= ((unsigned)((cur - prev) & 7)) << (5 + 3 * (k - 1));
            prev = cur;
        }
        sw[blk * NA + a] = wv;
    }
    __syncthreads();

    // ---- accumulators: 8 px x 4 ch = 16 u64 (px index = x + 4y) ----
    unsigned long long acc[16];
    #pragma unroll
    for (int i = 0; i < 16; i++) acc[i] = 0ull;

#define STEP0(PX)                                                             \
    asm volatile("{\n\t"                                                      \
        ".reg .u32 rr;\n\t"                                                   \
        "bfe.u32 rr, %5, 0, 5;\n\t"                                           \
        "mad.lo.u32 %4, rr, 512, %6;\n\t"                                     \
        "ld.shared.v2.u64 {%2, %3}, [%4];\n\t"                                \
        "add.rn.f32x2 %0, %0, %2;\n\t"                                        \
        "add.rn.f32x2 %1, %1, %3;\n\t"                                        \
        "}"                                                                   \
        : "+l"(acc[2*(PX)]), "+l"(acc[2*(PX)+1]),                             \
          "+l"(v0), "+l"(v1), "=r"(ad)                                        \
        : "r"(wv), "r"(sA))

#define STEPD(PX, K)                                                          \
    asm volatile("{\n\t"                                                      \
        ".reg .pred p;\n\t .reg .s32 d;\n\t"                                  \
        "bfe.s32 d, %5, %6, 3;\n\t"                                           \
        "setp.ne.s32 p, d, 0;\n\t"                                            \
        "mad.lo.s32 %4, d, 512, %4;\n\t"                                      \
        "@p ld.shared.v2.u64 {%2, %3}, [%4];\n\t"                             \
        "add.rn.f32x2 %0, %0, %2;\n\t"                                        \
        "add.rn.f32x2 %1, %1, %3;\n\t"                                        \
        "}"                                                                   \
        : "+l"(acc[2*(PX)]), "+l"(acc[2*(PX)+1]),                             \
          "+l"(v0), "+l"(v1), "+r"(ad)                                        \
        : "r"(wv), "n"(5 + 3*((K)-1)))

#define DOSEG(F0, F1, Q0,Q1,Q2,Q3,Q4,Q5,Q6,Q7)                                \
    for (int f = (F0); f < (F1); f++) {                                       \
        asm volatile("cp.async.wait_group 0;\n" ::: "memory");                \
        __syncthreads();                                                      \
        if (f + 1 < NPHASE) stage(f + 1);                                     \
        unsigned bufa = bufa0 + (unsigned)((f & 1) * BUFB);                   \
        _Pragma("unroll")                                                     \
        for (int s2 = 0; s2 < PH; s2++) {                                     \
            unsigned wv = sw[swb + f * PH + s2];                              \
            unsigned sA = bufa + (unsigned)(s2 * (WR * 512));                 \
            unsigned long long v0 = 0, v1 = 0;                                \
            unsigned ad;                                                      \
            STEP0(Q0);    STEPD(Q1,1); STEPD(Q2,2); STEPD(Q3,3);              \
            STEPD(Q4,4);  STEPD(Q5,5); STEPD(Q6,6); STEPD(Q7,7);              \
        }                                                                     \
    }

    const unsigned swb = w * NA;
    unsigned bufa0 = (unsigned)__cvta_generic_to_shared(sbuf[0]) + (lane << 4);

    DOSEG( 0, 15, 0,4,1,5,2,6,3,7);   // a 0-44
    DOSEG(15, 21, 0,1,4,2,5,3,6,7);   // a 45-62
    DOSEG(21, 24, 0,1,2,4,3,5,6,7);   // a 63-71
    DOSEG(24, 30, 0,1,2,3,4,5,6,7);   // a 72-89
    DOSEG(30, 36, 3,2,1,0,7,6,5,4);   // a 90-107
    DOSEG(36, 39, 3,2,1,7,0,6,5,4);   // a 108-116
    DOSEG(39, 45, 3,2,7,1,6,0,5,4);   // a 117-134
    DOSEG(45, 60, 3,7,2,6,1,5,0,4);   // a 135-179
#undef DOSEG
#undef STEPD
#undef STEP0

    // ---- epilogue: per ch, per row: float4 over the 4-wide block ----
    const int gx = x0 + 4 * (w & 3);
    const int gy = y0 + 2 * (w >> 2);
    const int c0 = cz0 + lane * 4;
    #pragma unroll
    for (int y = 0; y < 2; y++) {
        #pragma unroll
        for (int cc = 0; cc < 4; cc++) {
            int half = cc & 1, sel = cc >> 1;
            float4 o;
            unsigned long long s0 = acc[(0 + 4*y)*2 + sel];
            unsigned long long s1 = acc[(1 + 4*y)*2 + sel];
            unsigned long long s2 = acc[(2 + 4*y)*2 + sel];
            unsigned long long s3 = acc[(3 + 4*y)*2 + sel];
            o.x = __uint_as_float(half ? (unsigned)(s0 >> 32) : (unsigned)s0);
            o.y = __uint_as_float(half ? (unsigned)(s1 >> 32) : (unsigned)s1);
            o.z = __uint_as_float(half ? (unsigned)(s2 >> 32) : (unsigned)s2);
            o.w = __uint_as_float(half ? (unsigned)(s3 >> 32) : (unsigned)s3);
            *(float4*)(out + (size_t)(c0 + cc) * PIX + (gy + y) * WW + gx) = o;
        }
    }
}

// ---------------------------------------------------------------------------
extern "C" void kernel_launch(void* const* d_in, const int* in_sizes, int n_in,
                              void* d_out, int out_size)
{
    const float* hough = (const float*)d_in[0];
    float* out = (float*)d_out;

    tab_kernel<<<1, 256>>>();
    build_idx_kernel<<<dim3(PIX / 1024, NA), 256>>>();
    transpose_kernel<<<dim3(AR / 48, NC / 32), dim3(32, 12)>>>(hough);
    iht_main_kernel<<<dim3(10, 20, 8), TPB>>>(out);
}